// round 13
// baseline (speedup 1.0000x reference)
#include <cuda_runtime.h>
#include <cuda_bf16.h>
#include <cuda_fp16.h>
#include <math.h>
#include <stdint.h>

#define NB 8
#define CCH 256
#define HW 4096
#define EPSF 1e-6f
#define NIC 8   /* i-chunks for colpart */

// ---- scratch (device globals) ----
__device__ float g_ymu_part[NB * CCH];
__device__ float g_ymu[CCH];
__device__ __nv_bfloat16 g_xn[(size_t)NB * HW * CCH];
__device__ __nv_bfloat16 g_yn[(size_t)NB * HW * CCH];
__device__ __half g_D[(size_t)NB * HW * HW];
__device__ float2 g_ab[(size_t)NB * HW];
__device__ float g_part[(size_t)NB * NIC * HW];
__device__ float g_accum[NB];

__device__ __forceinline__ uint32_t smem_u32(const void* p) {
    uint32_t a;
    asm("{ .reg .u64 t; cvta.to.shared.u64 t, %1; cvt.u32.u64 %0, t; }" : "=r"(a) : "l"(p));
    return a;
}
__device__ __forceinline__ void mma_bf16(float* c, const uint32_t* a, const uint32_t* b) {
    asm volatile(
        "mma.sync.aligned.m16n8k16.row.col.f32.bf16.bf16.f32 "
        "{%0,%1,%2,%3}, {%4,%5,%6,%7}, {%8,%9}, {%0,%1,%2,%3};"
        : "+f"(c[0]), "+f"(c[1]), "+f"(c[2]), "+f"(c[3])
        : "r"(a[0]), "r"(a[1]), "r"(a[2]), "r"(a[3]), "r"(b[0]), "r"(b[1]));
}
__device__ __forceinline__ void ldsm_x4(uint32_t* r, uint32_t addr) {
    asm volatile("ldmatrix.sync.aligned.m8n8.x4.shared.b16 {%0,%1,%2,%3}, [%4];"
                 : "=r"(r[0]), "=r"(r[1]), "=r"(r[2]), "=r"(r[3]) : "r"(addr));
}
#define CP_ASYNC(dst, src) \
    asm volatile("cp.async.cg.shared.global [%0], [%1], 16;" :: "r"(dst), "l"(src))
#define CP_COMMIT() asm volatile("cp.async.commit_group;" ::: "memory")
#define CP_WAIT(n) asm volatile("cp.async.wait_group %0;" :: "n"(n) : "memory")

__device__ __forceinline__ uint32_t swz(int row, int ch) {
    return (uint32_t)(row * 64 + ((ch ^ ((row >> 1) & 3)) << 4));
}

// ---------------- K1a: per-(n,c) partial sum of y ----------------
__global__ void k_ymu_part(const float* __restrict__ y) {
    int c = blockIdx.x, n = blockIdx.y;
    const float* p = y + ((size_t)n * CCH + c) * HW;
    float s = 0.0f;
    #pragma unroll 4
    for (int t = threadIdx.x; t < HW; t += 256) s += p[t];
    #pragma unroll
    for (int o = 16; o > 0; o >>= 1)
        s += __shfl_xor_sync(0xffffffff, s, o);
    __shared__ float sh[8];
    if ((threadIdx.x & 31) == 0) sh[threadIdx.x >> 5] = s;
    __syncthreads();
    if (threadIdx.x == 0) {
        float t = 0.0f;
        #pragma unroll
        for (int w = 0; w < 8; w++) t += sh[w];
        g_ymu_part[n * CCH + c] = t;
    }
}
// K1b: reduce partials over n
__global__ void k_ymu_red() {
    int c = threadIdx.x;   // 256 threads
    float s = 0.0f;
    #pragma unroll
    for (int n = 0; n < NB; n++) s += g_ymu_part[n * CCH + c];
    g_ymu[c] = s * (1.0f / (NB * HW));
}

// ---------------- K2: center + normalize over C, transpose, bf16 ----------------
__global__ void k_norm(const float* __restrict__ x, const float* __restrict__ y) {
    const float* src = blockIdx.z ? y : x;
    __nv_bfloat16* dst = blockIdx.z ? g_yn : g_xn;
    int n = blockIdx.y;
    int i0 = blockIdx.x * 32;

    __shared__ float sh[32 * 257];
    __shared__ float inv[32];

    const float* base = src + (size_t)n * CCH * HW + i0;
    int tid = threadIdx.x;
    int p = tid & 31, cl = tid >> 5;

    for (int cc = cl; cc < CCH; cc += 8)
        sh[p * 257 + cc] = base[(size_t)cc * HW + p] - g_ymu[cc];
    __syncthreads();
    if (tid < 32) {
        float ss = 0.0f;
        #pragma unroll 8
        for (int c = 0; c < CCH; c++) {
            float v = sh[tid * 257 + c];
            ss += v * v;
        }
        inv[tid] = rsqrtf(ss);
    }
    __syncthreads();
    __nv_bfloat16* out = dst + ((size_t)n * HW + i0) * CCH;
    for (int idx = tid; idx < 32 * CCH; idx += 256) {
        int pp = idx >> 8, c = idx & 255;
        out[idx] = __float2bfloat16(sh[pp * 257 + c] * inv[pp]);
    }
}

// ---------------- K3: HMMA bf16 GEMM, BK=64, 3-stage (96KB smem) ----------------
// grid (32, 32, NB), block 256 (8 warps 4x2), CTA tile 128x128
#define STG 16384
#define B_BASE 49152
__global__ void __launch_bounds__(256, 2) k_gemm_mma() {
    extern __shared__ __align__(16) char smem[];

    int tid = threadIdx.x;
    int wid = tid >> 5, lane = tid & 31;
    int wm = wid >> 1, wn = wid & 1;

    int n = blockIdx.z;
    int i0 = blockIdx.x * 128, j0 = blockIdx.y * 128;

    const __nv_bfloat16* A = g_xn + ((size_t)n * HW + i0) * CCH;
    const __nv_bfloat16* B = g_yn + ((size_t)n * HW + j0) * CCH;

    uint32_t sbase = smem_u32(smem);

    int r0 = tid >> 2, c0 = tid & 3;
    int r1 = r0 + 64;
    uint32_t d0 = swz(r0, c0), d1 = swz(r1, c0);

    float acc[2][8][4];
    #pragma unroll
    for (int mf = 0; mf < 2; mf++)
        #pragma unroll
        for (int nf = 0; nf < 8; nf++)
            #pragma unroll
            for (int q = 0; q < 4; q++) acc[mf][nf][q] = 0.0f;

    int rowA[2], cAbase;
    {
        int m_in = lane & 15;
        cAbase = lane >> 4;
        rowA[0] = wm * 32 + m_in;
        rowA[1] = wm * 32 + 16 + m_in;
    }
    int rowB[4], cBbase;
    {
        int grp = lane >> 3;
        int n_off = (grp >> 1) * 8;
        cBbase = grp & 1;
        #pragma unroll
        for (int g = 0; g < 4; g++)
            rowB[g] = wn * 64 + g * 16 + n_off + (lane & 7);
    }

    #define LOAD_STAGE(st) do { \
        int k0_ = (st) * 64; \
        uint32_t soA_ = (uint32_t)((st) % 3) * STG; \
        uint32_t soB_ = B_BASE + (uint32_t)((st) % 3) * STG; \
        _Pragma("unroll") \
        for (int sub = 0; sub < 2; sub++) { \
            CP_ASYNC(sbase + soA_ + sub * 8192 + d0, A + (size_t)r0 * CCH + k0_ + sub * 32 + c0 * 8); \
            CP_ASYNC(sbase + soA_ + sub * 8192 + d1, A + (size_t)r1 * CCH + k0_ + sub * 32 + c0 * 8); \
            CP_ASYNC(sbase + soB_ + sub * 8192 + d0, B + (size_t)r0 * CCH + k0_ + sub * 32 + c0 * 8); \
            CP_ASYNC(sbase + soB_ + sub * 8192 + d1, B + (size_t)r1 * CCH + k0_ + sub * 32 + c0 * 8); \
        } \
    } while (0)

    LOAD_STAGE(0); CP_COMMIT();
    LOAD_STAGE(1); CP_COMMIT();

    #pragma unroll 1
    for (int s = 0; s < 4; s++) {
        CP_WAIT(1);
        __syncthreads();

        if (s + 2 < 4) LOAD_STAGE(s + 2);
        CP_COMMIT();

        uint32_t sA0 = sbase + (uint32_t)(s % 3) * STG;
        uint32_t sB0 = sbase + B_BASE + (uint32_t)(s % 3) * STG;

        #pragma unroll
        for (int t = 0; t < 4; t++) {
            uint32_t sA = sA0 + (uint32_t)(t >> 1) * 8192;
            uint32_t sB = sB0 + (uint32_t)(t >> 1) * 8192;
            int kc = (t & 1) * 2;
            uint32_t a[2][4];
            #pragma unroll
            for (int mf = 0; mf < 2; mf++) {
                int row = rowA[mf];
                uint32_t addr = sA + (uint32_t)(row * 64 + (((cAbase + kc) ^ ((row >> 1) & 3)) << 4));
                ldsm_x4(a[mf], addr);
            }
            uint32_t breg[16];
            #pragma unroll
            for (int g = 0; g < 4; g++) {
                int row = rowB[g];
                uint32_t addr = sB + (uint32_t)(row * 64 + (((cBbase + kc) ^ ((row >> 1) & 3)) << 4));
                ldsm_x4(breg + g * 4, addr);
            }
            #pragma unroll
            for (int mf = 0; mf < 2; mf++)
                #pragma unroll
                for (int nf = 0; nf < 8; nf++)
                    mma_bf16(acc[mf][nf], a[mf], breg + ((nf >> 1) * 4 + (nf & 1) * 2));
        }
    }

    // epilogue: D = 1 - acc (fp16)
    __half* Dn = g_D + (size_t)n * HW * HW;
    int rbase = i0 + wm * 32 + (lane >> 2);
    int cbase = j0 + wn * 64 + (lane & 3) * 2;
    #pragma unroll
    for (int mf = 0; mf < 2; mf++) {
        #pragma unroll
        for (int nf = 0; nf < 8; nf++) {
            int col = cbase + nf * 8;
            int rr = rbase + mf * 16;
            __half2 h0 = __floats2half2_rn(1.0f - acc[mf][nf][0], 1.0f - acc[mf][nf][1]);
            __half2 h1 = __floats2half2_rn(1.0f - acc[mf][nf][2], 1.0f - acc[mf][nf][3]);
            *reinterpret_cast<__half2*>(Dn + (size_t)rr * HW + col) = h0;
            *reinterpret_cast<__half2*>(Dn + (size_t)(rr + 8) * HW + col) = h1;
        }
    }
}

// ---------------- K4: warp-per-row min + sum -> (a, b) ----------------
// grid (HW/8, NB), block 256 (8 warps)
__global__ void __launch_bounds__(256) k_minsum() {
    int warp = threadIdx.x >> 5, lane = threadIdx.x & 31;
    int i = blockIdx.x * 8 + warp;
    int n = blockIdx.y;
    const uint4* row = reinterpret_cast<const uint4*>(g_D + ((size_t)n * HW + i) * HW);

    uint4 v[16];
    #pragma unroll
    for (int t = 0; t < 16; t++) v[t] = row[t * 32 + lane];

    __half2 m2 = __floats2half2_rn(6.0e4f, 6.0e4f);
    #pragma unroll
    for (int t = 0; t < 16; t++) {
        const __half2* h = reinterpret_cast<const __half2*>(&v[t]);
        m2 = __hmin2(m2, __hmin2(__hmin2(h[0], h[1]), __hmin2(h[2], h[3])));
    }
    float mn = fminf(__low2float(m2), __high2float(m2));
    #pragma unroll
    for (int o = 16; o > 0; o >>= 1)
        mn = fminf(mn, __shfl_xor_sync(0xffffffff, mn, o));

    float a = 2.0f / (mn + EPSF);
    float s = 0.0f;
    #pragma unroll
    for (int t = 0; t < 16; t++) {
        const __half2* h = reinterpret_cast<const __half2*>(&v[t]);
        #pragma unroll
        for (int q = 0; q < 4; q++) {
            float2 f = __half22float2(h[q]);
            s += __expf(fmaf(-a, f.x, 2.0f)) + __expf(fmaf(-a, f.y, 2.0f));
        }
    }
    #pragma unroll
    for (int o = 16; o > 0; o >>= 1)
        s += __shfl_xor_sync(0xffffffff, s, o);

    if (lane == 0)
        g_ab[(size_t)n * HW + i] = make_float2(a, 2.0f - __logf(s));
}

// ---------------- K5: partial column max of (b_i - a_i*d_ij) over i-chunks ----------------
// grid (8 jb, NIC ic, NB), block 512
__global__ void __launch_bounds__(512) k_colpart() {
    int n = blockIdx.z, ic = blockIdx.y, jb = blockIdx.x;
    int tid = threadIdx.x;
    int jl = tid & 255, iq = tid >> 8;
    int j = jb * 512 + jl * 2;
    const __half2* W = reinterpret_cast<const __half2*>(g_D + (size_t)n * HW * HW + j);
    const float2* ab = g_ab + (size_t)n * HW;
    const int CH = HW / NIC;   // 512 rows per chunk

    float2 m = make_float2(-3.4e38f, -3.4e38f);
    int ibase = ic * CH;
    #pragma unroll 4
    for (int ii = iq; ii < CH; ii += 2) {
        int i = ibase + ii;
        float2 f = __half22float2(W[(size_t)i * (HW / 2)]);
        float2 t = __ldg(&ab[i]);
        m.x = fmaxf(m.x, fmaf(-t.x, f.x, t.y));
        m.y = fmaxf(m.y, fmaf(-t.x, f.y, t.y));
    }
    __shared__ float2 sm[512];
    sm[tid] = m;
    __syncthreads();
    if (tid < 256) {
        float2 o = sm[tid + 256];
        m = sm[tid];
        m.x = fmaxf(m.x, o.x);
        m.y = fmaxf(m.y, o.y);
        *reinterpret_cast<float2*>(&g_part[((size_t)n * NIC + ic) * HW + j]) = m;
    }
}

// ---------------- K6: reduce partials ----------------
__global__ void k_colreduce() {
    int n = blockIdx.x, tid = threadIdx.x;
    float s = 0.0f;
    #pragma unroll
    for (int k = 0; k < 4; k++) {
        int j = tid + k * 1024;
        float m = -3.4e38f;
        #pragma unroll
        for (int ic = 0; ic < NIC; ic++)
            m = fmaxf(m, g_part[((size_t)n * NIC + ic) * HW + j]);
        s += __expf(m);
    }
    __shared__ float sh[1024];
    sh[tid] = s;
    __syncthreads();
    for (int o = 512; o > 0; o >>= 1) {
        if (tid < o) sh[tid] += sh[tid + o];
        __syncthreads();
    }
    if (tid == 0) g_accum[n] = sh[0];
}

// ---------------- K7: final loss ----------------
__global__ void k_final(float* __restrict__ out) {
    if (threadIdx.x == 0) {
        float s = 0.0f;
        for (int n = 0; n < NB; n++)
            s += -logf(g_accum[n] * (1.0f / HW) + EPSF);
        out[0] = s * (1.0f / NB);
    }
}

extern "C" void kernel_launch(void* const* d_in, const int* in_sizes, int n_in,
                              void* d_out, int out_size) {
    const float* x = (const float*)d_in[0];
    const float* y = (const float*)d_in[1];
    float* out = (float*)d_out;

    cudaFuncSetAttribute(k_gemm_mma, cudaFuncAttributeMaxDynamicSharedMemorySize, 98304);

    k_ymu_part<<<dim3(CCH, NB), 256>>>(y);
    k_ymu_red<<<1, 256>>>();
    k_norm<<<dim3(HW / 32, NB, 2), 256>>>(x, y);
    k_gemm_mma<<<dim3(HW / 128, HW / 128, NB), 256, 98304>>>();
    k_minsum<<<dim3(HW / 8, NB), 256>>>();
    k_colpart<<<dim3(8, NIC, NB), 512>>>();
    k_colreduce<<<NB, 1024>>>();
    k_final<<<1, 32>>>(out);
}

// round 14
// speedup vs baseline: 1.4076x; 1.4076x over previous
#include <cuda_runtime.h>
#include <cuda_bf16.h>
#include <cuda_fp16.h>
#include <math.h>
#include <stdint.h>

#define NB 8
#define CCH 256
#define HW 4096
#define EPSF 1e-6f
#define NIC 8   /* i-chunks for colpart */

// ---- scratch (device globals) ----
__device__ float g_ymu_part[NB * CCH];
__device__ float g_ymu[CCH];
__device__ __nv_bfloat16 g_xn[(size_t)NB * HW * CCH];
__device__ __nv_bfloat16 g_yn[(size_t)NB * HW * CCH];
__device__ __half g_D[(size_t)NB * HW * HW];
__device__ float2 g_ab[(size_t)NB * HW];
__device__ float g_part[(size_t)NB * NIC * HW];
__device__ float g_accum[NB];

__device__ __forceinline__ uint32_t smem_u32(const void* p) {
    uint32_t a;
    asm("{ .reg .u64 t; cvta.to.shared.u64 t, %1; cvt.u32.u64 %0, t; }" : "=r"(a) : "l"(p));
    return a;
}
__device__ __forceinline__ void mma_bf16(float* c, const uint32_t* a, const uint32_t* b) {
    asm volatile(
        "mma.sync.aligned.m16n8k16.row.col.f32.bf16.bf16.f32 "
        "{%0,%1,%2,%3}, {%4,%5,%6,%7}, {%8,%9}, {%0,%1,%2,%3};"
        : "+f"(c[0]), "+f"(c[1]), "+f"(c[2]), "+f"(c[3])
        : "r"(a[0]), "r"(a[1]), "r"(a[2]), "r"(a[3]), "r"(b[0]), "r"(b[1]));
}
__device__ __forceinline__ void ldsm_x4(uint32_t* r, uint32_t addr) {
    asm volatile("ldmatrix.sync.aligned.m8n8.x4.shared.b16 {%0,%1,%2,%3}, [%4];"
                 : "=r"(r[0]), "=r"(r[1]), "=r"(r[2]), "=r"(r[3]) : "r"(addr));
}
#define CP_ASYNC(dst, src) \
    asm volatile("cp.async.cg.shared.global [%0], [%1], 16;" :: "r"(dst), "l"(src))
#define CP_COMMIT() asm volatile("cp.async.commit_group;" ::: "memory")
#define CP_WAIT(n) asm volatile("cp.async.wait_group %0;" :: "n"(n) : "memory")

__device__ __forceinline__ uint32_t swz(int row, int ch) {
    return (uint32_t)(row * 64 + ((ch ^ ((row >> 1) & 3)) << 4));
}

// ---------------- K1a: per-(n,c) partial sum of y ----------------
__global__ void k_ymu_part(const float* __restrict__ y) {
    int c = blockIdx.x, n = blockIdx.y;
    const float* p = y + ((size_t)n * CCH + c) * HW;
    float s = 0.0f;
    #pragma unroll 4
    for (int t = threadIdx.x; t < HW; t += 256) s += p[t];
    #pragma unroll
    for (int o = 16; o > 0; o >>= 1)
        s += __shfl_xor_sync(0xffffffff, s, o);
    __shared__ float sh[8];
    if ((threadIdx.x & 31) == 0) sh[threadIdx.x >> 5] = s;
    __syncthreads();
    if (threadIdx.x == 0) {
        float t = 0.0f;
        #pragma unroll
        for (int w = 0; w < 8; w++) t += sh[w];
        g_ymu_part[n * CCH + c] = t;
    }
}
// K1b: reduce partials over n
__global__ void k_ymu_red() {
    int c = threadIdx.x;   // 256 threads
    float s = 0.0f;
    #pragma unroll
    for (int n = 0; n < NB; n++) s += g_ymu_part[n * CCH + c];
    g_ymu[c] = s * (1.0f / (NB * HW));
}

// ---------------- K2: center + normalize over C, transpose, bf16 ----------------
__global__ void k_norm(const float* __restrict__ x, const float* __restrict__ y) {
    const float* src = blockIdx.z ? y : x;
    __nv_bfloat16* dst = blockIdx.z ? g_yn : g_xn;
    int n = blockIdx.y;
    int i0 = blockIdx.x * 32;

    __shared__ float sh[32 * 257];
    __shared__ float inv[32];

    const float* base = src + (size_t)n * CCH * HW + i0;
    int tid = threadIdx.x;
    int p = tid & 31, cl = tid >> 5;

    for (int cc = cl; cc < CCH; cc += 8)
        sh[p * 257 + cc] = base[(size_t)cc * HW + p] - g_ymu[cc];
    __syncthreads();
    if (tid < 32) {
        float ss = 0.0f;
        #pragma unroll 8
        for (int c = 0; c < CCH; c++) {
            float v = sh[tid * 257 + c];
            ss += v * v;
        }
        inv[tid] = rsqrtf(ss);
    }
    __syncthreads();
    __nv_bfloat16* out = dst + ((size_t)n * HW + i0) * CCH;
    for (int idx = tid; idx < 32 * CCH; idx += 256) {
        int pp = idx >> 8, c = idx & 255;
        out[idx] = __float2bfloat16(sh[pp * 257 + c] * inv[pp]);
    }
}

// ---------------- K3: HMMA bf16 GEMM, BK=32, 4-stage (64KB smem), staged epilogue ----------------
// grid (32, 32, NB), block 256 (8 warps: 4 in M x 2 in N), CTA tile 128x128
#define TROW 272   /* epilogue tile row stride in bytes: 128 half + 8 pad */
__global__ void __launch_bounds__(256, 2) k_gemm_mma() {
    extern __shared__ __align__(16) char smem[];   // 4 stages A (8KB) + 4 stages B (8KB)

    int tid = threadIdx.x;
    int wid = tid >> 5, lane = tid & 31;
    int wm = wid >> 1, wn = wid & 1;

    int n = blockIdx.z;
    int i0 = blockIdx.x * 128, j0 = blockIdx.y * 128;

    const __nv_bfloat16* A = g_xn + ((size_t)n * HW + i0) * CCH;
    const __nv_bfloat16* B = g_yn + ((size_t)n * HW + j0) * CCH;

    uint32_t sbase = smem_u32(smem);
    const uint32_t B_OFF = 32768;

    int r0 = tid >> 2, c0 = tid & 3;
    int r1 = r0 + 64;
    uint32_t dA0 = swz(r0, c0), dA1 = swz(r1, c0);

    float acc[2][8][4];
    #pragma unroll
    for (int mf = 0; mf < 2; mf++)
        #pragma unroll
        for (int nf = 0; nf < 8; nf++)
            #pragma unroll
            for (int q = 0; q < 4; q++) acc[mf][nf][q] = 0.0f;

    int rowA[2], cAbase;
    {
        int m_in = lane & 15;
        cAbase = lane >> 4;
        rowA[0] = wm * 32 + m_in;
        rowA[1] = wm * 32 + 16 + m_in;
    }
    int rowB[4], cBbase;
    {
        int grp = lane >> 3;
        int n_off = (grp >> 1) * 8;
        cBbase = grp & 1;
        #pragma unroll
        for (int g = 0; g < 4; g++)
            rowB[g] = wn * 64 + g * 16 + n_off + (lane & 7);
    }

    // prologue: prefetch stages 0,1,2
    #pragma unroll
    for (int s = 0; s < 3; s++) {
        int k0 = s * 32;
        uint32_t so = (uint32_t)s * 8192;
        CP_ASYNC(sbase + so + dA0, A + (size_t)r0 * CCH + k0 + c0 * 8);
        CP_ASYNC(sbase + so + dA1, A + (size_t)r1 * CCH + k0 + c0 * 8);
        CP_ASYNC(sbase + B_OFF + so + dA0, B + (size_t)r0 * CCH + k0 + c0 * 8);
        CP_ASYNC(sbase + B_OFF + so + dA1, B + (size_t)r1 * CCH + k0 + c0 * 8);
        CP_COMMIT();
    }

    #pragma unroll 1
    for (int s = 0; s < 8; s++) {
        CP_WAIT(2);
        __syncthreads();

        if (s + 3 < 8) {
            int k0 = (s + 3) * 32;
            uint32_t so = (uint32_t)((s + 3) & 3) * 8192;
            CP_ASYNC(sbase + so + dA0, A + (size_t)r0 * CCH + k0 + c0 * 8);
            CP_ASYNC(sbase + so + dA1, A + (size_t)r1 * CCH + k0 + c0 * 8);
            CP_ASYNC(sbase + B_OFF + so + dA0, B + (size_t)r0 * CCH + k0 + c0 * 8);
            CP_ASYNC(sbase + B_OFF + so + dA1, B + (size_t)r1 * CCH + k0 + c0 * 8);
        }
        CP_COMMIT();

        uint32_t sA = sbase + (uint32_t)(s & 3) * 8192;
        uint32_t sB = sbase + B_OFF + (uint32_t)(s & 3) * 8192;

        #pragma unroll
        for (int t = 0; t < 2; t++) {
            int kc = t * 2;
            uint32_t a[2][4];
            #pragma unroll
            for (int mf = 0; mf < 2; mf++) {
                int row = rowA[mf];
                uint32_t addr = sA + (uint32_t)(row * 64 + (((cAbase + kc) ^ ((row >> 1) & 3)) << 4));
                ldsm_x4(a[mf], addr);
            }
            uint32_t breg[16];
            #pragma unroll
            for (int g = 0; g < 4; g++) {
                int row = rowB[g];
                uint32_t addr = sB + (uint32_t)(row * 64 + (((cBbase + kc) ^ ((row >> 1) & 3)) << 4));
                ldsm_x4(breg + g * 4, addr);
            }
            #pragma unroll
            for (int mf = 0; mf < 2; mf++)
                #pragma unroll
                for (int nf = 0; nf < 8; nf++)
                    mma_bf16(acc[mf][nf], a[mf], breg + ((nf >> 1) * 4 + (nf & 1) * 2));
        }
    }

    // ---- staged epilogue: scatter to smem tile (padded), then coalesced STG.128 ----
    CP_WAIT(0);
    __syncthreads();   // all reads of pipeline smem done

    {
        int rrel0 = wm * 32 + (lane >> 2);
        int crel = wn * 64 + (lane & 3) * 2;
        #pragma unroll
        for (int mf = 0; mf < 2; mf++) {
            #pragma unroll
            for (int nf = 0; nf < 8; nf++) {
                int r = rrel0 + mf * 16;
                int c = crel + nf * 8;
                __half2 h0 = __floats2half2_rn(1.0f - acc[mf][nf][0], 1.0f - acc[mf][nf][1]);
                __half2 h1 = __floats2half2_rn(1.0f - acc[mf][nf][2], 1.0f - acc[mf][nf][3]);
                *reinterpret_cast<__half2*>(smem + r * TROW + c * 2) = h0;
                *reinterpret_cast<__half2*>(smem + (r + 8) * TROW + c * 2) = h1;
            }
        }
    }
    __syncthreads();

    {
        __half* Dn = g_D + (size_t)n * HW * HW;
        #pragma unroll
        for (int k = 0; k < 8; k++) {
            int idx = tid + 256 * k;          // 2048 uint4 = 32KB
            int row = idx >> 4, ch = idx & 15;
            uint4 v = *reinterpret_cast<const uint4*>(smem + row * TROW + ch * 16);
            *reinterpret_cast<uint4*>(Dn + (size_t)(i0 + row) * HW + j0 + ch * 8) = v;
        }
    }
}

// ---------------- K4: warp-per-row min + sum -> (a, b) ----------------
// grid (HW/8, NB), block 256 (8 warps)
__global__ void __launch_bounds__(256) k_minsum() {
    int warp = threadIdx.x >> 5, lane = threadIdx.x & 31;
    int i = blockIdx.x * 8 + warp;
    int n = blockIdx.y;
    const uint4* row = reinterpret_cast<const uint4*>(g_D + ((size_t)n * HW + i) * HW);

    uint4 v[16];
    #pragma unroll
    for (int t = 0; t < 16; t++) v[t] = row[t * 32 + lane];

    __half2 m2 = __floats2half2_rn(6.0e4f, 6.0e4f);
    #pragma unroll
    for (int t = 0; t < 16; t++) {
        const __half2* h = reinterpret_cast<const __half2*>(&v[t]);
        m2 = __hmin2(m2, __hmin2(__hmin2(h[0], h[1]), __hmin2(h[2], h[3])));
    }
    float mn = fminf(__low2float(m2), __high2float(m2));
    #pragma unroll
    for (int o = 16; o > 0; o >>= 1)
        mn = fminf(mn, __shfl_xor_sync(0xffffffff, mn, o));

    float a = 2.0f / (mn + EPSF);
    float s = 0.0f;
    #pragma unroll
    for (int t = 0; t < 16; t++) {
        const __half2* h = reinterpret_cast<const __half2*>(&v[t]);
        #pragma unroll
        for (int q = 0; q < 4; q++) {
            float2 f = __half22float2(h[q]);
            s += __expf(fmaf(-a, f.x, 2.0f)) + __expf(fmaf(-a, f.y, 2.0f));
        }
    }
    #pragma unroll
    for (int o = 16; o > 0; o >>= 1)
        s += __shfl_xor_sync(0xffffffff, s, o);

    if (lane == 0)
        g_ab[(size_t)n * HW + i] = make_float2(a, 2.0f - __logf(s));
}

// ---------------- K5: partial column max of (b_i - a_i*d_ij) over i-chunks ----------------
// grid (8 jb, NIC ic, NB), block 512
__global__ void __launch_bounds__(512) k_colpart() {
    int n = blockIdx.z, ic = blockIdx.y, jb = blockIdx.x;
    int tid = threadIdx.x;
    int jl = tid & 255, iq = tid >> 8;
    int j = jb * 512 + jl * 2;
    const __half2* W = reinterpret_cast<const __half2*>(g_D + (size_t)n * HW * HW + j);
    const float2* ab = g_ab + (size_t)n * HW;
    const int CH = HW / NIC;   // 512 rows per chunk

    float2 m = make_float2(-3.4e38f, -3.4e38f);
    int ibase = ic * CH;
    #pragma unroll 4
    for (int ii = iq; ii < CH; ii += 2) {
        int i = ibase + ii;
        float2 f = __half22float2(W[(size_t)i * (HW / 2)]);
        float2 t = __ldg(&ab[i]);
        m.x = fmaxf(m.x, fmaf(-t.x, f.x, t.y));
        m.y = fmaxf(m.y, fmaf(-t.x, f.y, t.y));
    }
    __shared__ float2 sm[512];
    sm[tid] = m;
    __syncthreads();
    if (tid < 256) {
        float2 o = sm[tid + 256];
        m = sm[tid];
        m.x = fmaxf(m.x, o.x);
        m.y = fmaxf(m.y, o.y);
        *reinterpret_cast<float2*>(&g_part[((size_t)n * NIC + ic) * HW + j]) = m;
    }
}

// ---------------- K6: reduce partials ----------------
__global__ void k_colreduce() {
    int n = blockIdx.x, tid = threadIdx.x;
    float s = 0.0f;
    #pragma unroll
    for (int k = 0; k < 4; k++) {
        int j = tid + k * 1024;
        float m = -3.4e38f;
        #pragma unroll
        for (int ic = 0; ic < NIC; ic++)
            m = fmaxf(m, g_part[((size_t)n * NIC + ic) * HW + j]);
        s += __expf(m);
    }
    __shared__ float sh[1024];
    sh[tid] = s;
    __syncthreads();
    for (int o = 512; o > 0; o >>= 1) {
        if (tid < o) sh[tid] += sh[tid + o];
        __syncthreads();
    }
    if (tid == 0) g_accum[n] = sh[0];
}

// ---------------- K7: final loss ----------------
__global__ void k_final(float* __restrict__ out) {
    if (threadIdx.x == 0) {
        float s = 0.0f;
        for (int n = 0; n < NB; n++)
            s += -logf(g_accum[n] * (1.0f / HW) + EPSF);
        out[0] = s * (1.0f / NB);
    }
}

extern "C" void kernel_launch(void* const* d_in, const int* in_sizes, int n_in,
                              void* d_out, int out_size) {
    const float* x = (const float*)d_in[0];
    const float* y = (const float*)d_in[1];
    float* out = (float*)d_out;

    cudaFuncSetAttribute(k_gemm_mma, cudaFuncAttributeMaxDynamicSharedMemorySize, 65536);

    k_ymu_part<<<dim3(CCH, NB), 256>>>(y);
    k_ymu_red<<<1, 256>>>();
    k_norm<<<dim3(HW / 32, NB, 2), 256>>>(x, y);
    k_gemm_mma<<<dim3(HW / 128, HW / 128, NB), 256, 65536>>>();
    k_minsum<<<dim3(HW / 8, NB), 256>>>();
    k_colpart<<<dim3(8, NIC, NB), 512>>>();
    k_colreduce<<<NB, 1024>>>();
    k_final<<<1, 32>>>(out);
}